// round 10
// baseline (speedup 1.0000x reference)
#include <cuda_runtime.h>
#include <cstdint>

// Fixed shapes: B=1, N=64, X=256, Y=256, Z=32
#define NINST 64
#define V (256*256*32)            // 2,097,152 floats / instance
#define WPI (V/32)                // 65536 packed words / instance
#define NSLICE 512                // k-slices of 128 words
#define SLICE_W 128               // words per slice (per instance)
#define NPACK 256                 // packer blocks (64 inst x 4 quarters)
#define NBLK 444                  // one full wave (148 SMs x 3)
#define NTHR 256
#define NSLOT 8
#define PWORDS (WPI/4)            // 16384 words per packer block
#define PCELLS (PWORDS/SLICE_W)   // 128 cells per packer block

// Device state (zero-init at load; last block resets -> replays start clean).
// g_pk4: packed bits, [k4][inst] uint4 = words [4k4,4k4+4) of instance inst.
__device__ uint4    g_pk4[(WPI/4) * NINST];      // 16 MB (never needs reset)
__device__ unsigned g_cnt[NSLICE];               // words-done per k-slice
__device__ unsigned g_partial[NSLOT * NINST * NINST];
__device__ unsigned g_score[NINST];
__device__ unsigned g_ticket;
__device__ unsigned g_done;

__global__ __launch_bounds__(NTHR, 3) void fused_nms_kernel(
    const float* __restrict__ mask, float* __restrict__ out)
{
    __shared__ unsigned sm_pk[SLICE_W][NINST];   // 32 KB (tail reuses as inter)
    __shared__ unsigned ssc[NINST];
    __shared__ int s_slice, s_done;

    const int tid  = threadIdx.x;
    const int lane = tid & 31;
    const int wp   = tid >> 5;

    if (blockIdx.x < NPACK) {
        // ===================== PACKER =====================
        // Block p packs instance p>>2, word quarter p&3: a CONTIGUOUS 2MB
        // gmem read. Word (it*16 + qq*4 + c) of a cell holds voxels
        // {cell*4096 + it*512 + qq*128 + 4l + c} — a fixed permutation,
        // identical for every instance, so pairwise popcounts are exact.
        const int p = blockIdx.x, inst = p >> 2, q = p & 3;
        const unsigned* base = (const unsigned*)mask +
            (size_t)inst * V + (size_t)q * PWORDS * 32;
        const int s0 = q * SLICE_W;      // this band's first slice id
        unsigned sc = 0;

        for (int cell = wp; cell < PCELLS; cell += 8) {
            const unsigned* cs = base + (size_t)cell * 4096 + lane * 4;
            const int k40 = q * (PWORDS / 4) + cell * 32;   // global k4 base

            // 2-deep software pipeline over 8 iterations of 16 words (2KB).
            uint4 a0 = __ldcs((const uint4*)(cs +   0));
            uint4 a1 = __ldcs((const uint4*)(cs + 128));
            uint4 a2 = __ldcs((const uint4*)(cs + 256));
            uint4 a3 = __ldcs((const uint4*)(cs + 384));
            uint4 b0 = __ldcs((const uint4*)(cs + 512));
            uint4 b1 = __ldcs((const uint4*)(cs + 640));
            uint4 b2 = __ldcs((const uint4*)(cs + 768));
            uint4 b3 = __ldcs((const uint4*)(cs + 896));

#pragma unroll
            for (int it = 0; it < 8; it++) {
                uint4 u0 = a0, u1 = a1, u2 = a2, u3 = a3;
                a0 = b0; a1 = b1; a2 = b2; a3 = b3;
                if (it < 6) {
                    const unsigned* nx = cs + (size_t)(it + 2) * 512;
                    b0 = __ldcs((const uint4*)(nx +   0));
                    b1 = __ldcs((const uint4*)(nx + 128));
                    b2 = __ldcs((const uint4*)(nx + 256));
                    b3 = __ldcs((const uint4*)(nx + 384));
                }
                unsigned bb[16];
#define B4(u, o) \
                bb[(o)+0] = __ballot_sync(0xffffffffu, (u).x != 0u); \
                bb[(o)+1] = __ballot_sync(0xffffffffu, (u).y != 0u); \
                bb[(o)+2] = __ballot_sync(0xffffffffu, (u).z != 0u); \
                bb[(o)+3] = __ballot_sync(0xffffffffu, (u).w != 0u);
                B4(u0, 0) B4(u1, 4) B4(u2, 8) B4(u3, 12)
#undef B4
                // Lanes 0-3 each assemble 4 consecutive words.
                uint4 ov;
                ov.x = lane==0?bb[0] : lane==1?bb[4] : lane==2?bb[8]  : bb[12];
                ov.y = lane==0?bb[1] : lane==1?bb[5] : lane==2?bb[9]  : bb[13];
                ov.z = lane==0?bb[2] : lane==1?bb[6] : lane==2?bb[10] : bb[14];
                ov.w = lane==0?bb[3] : lane==1?bb[7] : lane==2?bb[11] : bb[15];
                if (lane < 4) {
                    __stcg(&g_pk4[(k40 + it * 4 + lane) * NINST + inst], ov);
                    sc += __popc(ov.x) + __popc(ov.y) +
                          __popc(ov.z) + __popc(ov.w);
                }
            }
            // Release this (inst, slice) cell: fence + count by the lanes
            // that performed the stores (per-thread release is sound).
            if (lane < 4) {
                __threadfence();
                atomicAdd(&g_cnt[s0 + cell], 32u);
            }
        }
        // Scores: lanes 0-3 hold partials; reduce, one atomic per warp.
        sc += __shfl_down_sync(0xffffffffu, sc, 2);
        sc += __shfl_down_sync(0xffffffffu, sc, 1);
        if (lane == 0) atomicAdd(&g_score[inst], sc);

    } else {
        // ===================== CONSUMER =====================
        // Work unit (tid<240): off-diag 4x4 tile k=tid>>1 (a<b), half h=tid&1
        // -> words [h*64, h*64+64) of each slice.
        int i0 = 0, j0 = 4, w0 = 0;
        if (tid < 240) {
            int k = tid >> 1, a = 0, rem = k;
            while (rem >= 15 - a) { rem -= 15 - a; a++; }
            i0 = a * 4; j0 = (a + 1 + rem) * 4;
            w0 = (tid & 1) * 64;
        }
        unsigned acc[4][4];
#pragma unroll
        for (int r = 0; r < 4; r++)
#pragma unroll
            for (int c2 = 0; c2 < 4; c2++) acc[r][c2] = 0u;

        for (;;) {
            if (tid == 0) {
                int t = (int)atomicAdd(&g_ticket, 1u);
                if (t >= NSLICE) s_slice = -1;
                else {
                    // band-interleaved order matches production order
                    int s = ((t & 3) << 7) | (t >> 2);
                    while (*(volatile unsigned*)&g_cnt[s] < 8192u)
                        __nanosleep(128);
                    __threadfence();   // acquire
                    s_slice = s;
                }
            }
            __syncthreads();
            const int s = s_slice;
            if (s < 0) break;

            // Stage slice (64 inst x 128 words = 32KB) from L2, transposed.
            // STS bank = ((wb+c)*64 + inst) % 32 = lane  -> conflict-free.
#pragma unroll
            for (int r = 0; r < 4; r++) {
                const int k4l = wp * 4 + r;                 // 0..31
                const uint4* gp = &g_pk4[(s * 32 + k4l) * NINST];
                uint4 va = __ldcg(gp + lane);               // inst = lane
                uint4 vb = __ldcg(gp + 32 + lane);          // inst = lane+32
                const int wb = k4l * 4;
                sm_pk[wb + 0][lane] = va.x; sm_pk[wb + 1][lane] = va.y;
                sm_pk[wb + 2][lane] = va.z; sm_pk[wb + 3][lane] = va.w;
                sm_pk[wb + 0][lane + 32] = vb.x; sm_pk[wb + 1][lane + 32] = vb.y;
                sm_pk[wb + 2][lane + 32] = vb.z; sm_pk[wb + 3][lane + 32] = vb.w;
            }
            __syncthreads();

            if (tid < 240) {
#pragma unroll 4
                for (int w = w0; w < w0 + 64; w += 2) {
                    uint4 A0 = *(const uint4*)&sm_pk[w][i0];
                    uint4 B0 = *(const uint4*)&sm_pk[w][j0];
                    uint4 A1 = *(const uint4*)&sm_pk[w + 1][i0];
                    uint4 B1 = *(const uint4*)&sm_pk[w + 1][j0];
                    unsigned ar0[4] = {A0.x, A0.y, A0.z, A0.w};
                    unsigned br0[4] = {B0.x, B0.y, B0.z, B0.w};
                    unsigned ar1[4] = {A1.x, A1.y, A1.z, A1.w};
                    unsigned br1[4] = {B1.x, B1.y, B1.z, B1.w};
#pragma unroll
                    for (int r = 0; r < 4; r++)
#pragma unroll
                        for (int c2 = 0; c2 < 4; c2++)
                            acc[r][c2] += __popc(ar0[r] & br0[c2]) +
                                          __popc(ar1[r] & br1[c2]);
                }
            }
            __syncthreads();   // protect sm_pk before next staging
        }

        if (tid < 240) {
            unsigned* gp = g_partial +
                (unsigned)(blockIdx.x & (NSLOT - 1)) * (NINST * NINST);
#pragma unroll
            for (int r = 0; r < 4; r++)
#pragma unroll
                for (int c2 = 0; c2 < 4; c2++)
                    atomicAdd(&gp[(i0 + r) * NINST + (j0 + c2)], acc[r][c2]);
        }
    }

    // ===================== completion + tail =====================
    __threadfence();
    __syncthreads();
    if (tid == 0) s_done = (int)atomicAdd(&g_done, 1u);
    __syncthreads();
    if (s_done != NBLK - 1) return;

    unsigned* inter = &sm_pk[0][0];   // 16KB needed; staging area is dead

    {   // reduce NSLOT slots (L1-bypassing)
        const uint4* gp4 = (const uint4*)g_partial;
        uint4* in4 = (uint4*)inter;
        for (int e = tid; e < (NINST * NINST) / 4; e += NTHR) {
            uint4 sum = make_uint4(0u, 0u, 0u, 0u);
#pragma unroll
            for (int k = 0; k < NSLOT; k++) {
                uint4 w = __ldcg(&gp4[k * (NINST * NINST / 4) + e]);
                sum.x += w.x; sum.y += w.y; sum.z += w.z; sum.w += w.w;
            }
            in4[e] = sum;
        }
        if (tid < NINST) ssc[tid] = __ldcg(&g_score[tid]);
    }
    __syncthreads();

    {   // symmetrize (lower-triangle tiles were never written)
        for (int e = tid; e < NINST * NINST; e += NTHR) {
            int i = e >> 6, j = e & 63;
            if (i > j) {
                unsigned hi = inter[j * NINST + i];
                unsigned lo = inter[e];
                inter[e] = hi > lo ? hi : lo;
            }
        }
    }

    {   // reset device state for the next graph replay
        uint4 z = make_uint4(0u, 0u, 0u, 0u);
        uint4* gz = (uint4*)g_partial;
        for (int e = tid; e < (NSLOT * NINST * NINST) / 4; e += NTHR) gz[e] = z;
        for (int e = tid; e < NSLICE; e += NTHR) g_cnt[e] = 0u;
        if (tid < NINST) g_score[tid] = 0u;
        if (tid == 0) { g_ticket = 0u; g_done = 0u; }
    }
    __syncthreads();

    if (tid < 32) {
        const unsigned sj0 = ssc[lane];
        const unsigned sj1 = ssc[lane + 32];
        unsigned long long ind = ~0ULL;

        for (int i = 0; i < NINST; i++) {
            if (!((ind >> i) & 1ULL)) continue;   // warp-uniform
            const unsigned si  = ssc[i];
            const unsigned in0 = inter[i * NINST + lane];
            const unsigned in1 = inter[i * NINST + lane + 32];
            // iou > 0.5 <=> 2*inter > union (exact integers; counts < 2^23)
            const bool h0 = (2u * in0 > si + sj0 - in0);
            const bool h1 = (2u * in1 > si + sj1 - in1);
            unsigned a0 = __ballot_sync(0xffffffffu, h0 && (si > sj0));
            unsigned a1 = __ballot_sync(0xffffffffu, h1 && (si > sj1));
            unsigned c0m = __ballot_sync(0xffffffffu, h0 && (sj0 > si));
            unsigned c1m = __ballot_sync(0xffffffffu, h1 && (sj1 > si));
            unsigned long long A  = ((unsigned long long)a1 << 32) | a0;
            unsigned long long Bm = ((unsigned long long)c1m << 32) | c0m;
            if (A) {
                int jb = __ffsll((long long)A) - 1;    // first break j
                unsigned long long before = (1ULL << jb) - 1ULL;
                if (Bm & before) ind &= ~(1ULL << i);  // earlier j beat i
                ind &= ~(1ULL << jb);
            } else if (Bm) {
                ind &= ~(1ULL << i);
            }
        }
        out[lane]      = (float)((ind >> lane) & 1ULL);
        out[lane + 32] = (float)((ind >> (lane + 32)) & 1ULL);
    }
}

// ---------------------------------------------------------------------------
extern "C" void kernel_launch(void* const* d_in, const int* in_sizes, int n_in,
                              void* d_out, int out_size) {
    const float* mask = (const float*)d_in[0];
    fused_nms_kernel<<<NBLK, NTHR>>>(mask, (float*)d_out);
}

// round 12
// speedup vs baseline: 1.3382x; 1.3382x over previous
#include <cuda_runtime.h>
#include <cstdint>

// Fixed shapes: B=1, N=64, X=256, Y=256, Z=32
#define NINST 64
#define V (256*256*32)              // 2,097,152 floats / instance
#define CHUNK_VOX 512               // voxels per chunk per instance
#define CHUNK_BYTES 2048            // bytes per instance-slice
#define CHUNK_WORDS 16              // packed words per chunk per instance
#define NCHUNK (V/CHUNK_VOX)        // 4096 chunks
#define STAGE_INST 8                // instances per pipeline stage
#define STAGE_BYTES (STAGE_INST*CHUNK_BYTES)  // 16 KB
#define DEPTH 4                     // stage ring depth
#define NTHR 288                    // 8 pack warps + 1 producer warp
#define NPACK_THR 256               // threads in the pack-warp group
#define NBLK 444                    // 148 SMs x 3 resident blocks
#define NSLOT 8

// Dynamic smem layout
#define SM_RAW    0                                   // 65536
#define SM_PACKED 65536                               //  8192 (2x16x64 u32)
#define SM_MBAR   73728                               //    64 (full[4],empty[4])
#define SM_DONE   73792
#define SMEM_REQ  73856

// Device state (zero-init at load; last block resets -> replays start clean).
__device__ unsigned g_partial[NSLOT * NINST * NINST];
__device__ unsigned g_score[NSLOT * NINST];
__device__ unsigned g_done;

// ---------------------------------------------------------------------------
__device__ __forceinline__ unsigned su32(const void* p) {
    return (unsigned)__cvta_generic_to_shared(p);
}
__device__ __forceinline__ void mbar_init(unsigned a, unsigned cnt) {
    asm volatile("mbarrier.init.shared.b64 [%0], %1;" :: "r"(a), "r"(cnt) : "memory");
}
__device__ __forceinline__ void mbar_expect_tx(unsigned a, unsigned tx) {
    asm volatile("mbarrier.arrive.expect_tx.shared.b64 _, [%0], %1;"
                 :: "r"(a), "r"(tx) : "memory");
}
__device__ __forceinline__ void mbar_arrive(unsigned a) {
    asm volatile("mbarrier.arrive.shared.b64 _, [%0];" :: "r"(a) : "memory");
}
__device__ __forceinline__ void mbar_wait(unsigned a, unsigned parity) {
    asm volatile(
        "{\n\t.reg .pred p;\n\t"
        "WAIT_%=:\n\t"
        "mbarrier.try_wait.parity.acquire.cta.shared::cta.b64 p, [%0], %1, 0x989680;\n\t"
        "@!p bra WAIT_%=;\n\t}"
        :: "r"(a), "r"(parity) : "memory");
}
__device__ __forceinline__ void tma_bulk(unsigned dst, const void* src,
                                         unsigned bytes, unsigned mbar) {
    asm volatile(
        "cp.async.bulk.shared::cta.global.mbarrier::complete_tx::bytes [%0], [%1], %2, [%3];"
        :: "r"(dst), "l"(src), "r"(bytes), "r"(mbar) : "memory");
}
__device__ __forceinline__ void fence_async() {
    asm volatile("fence.proxy.async.shared::cta;" ::: "memory");
}
// Partial-block barrier: ONLY the 8 pack warps (256 threads) participate.
__device__ __forceinline__ void pack_barrier() {
    asm volatile("bar.sync 1, %0;" :: "r"(NPACK_THR) : "memory");
}

extern __shared__ char smem[];

// ---------------------------------------------------------------------------
// Fused kernel, mbarrier-only load pipeline:
//  - producer warp (wp==8, lanes 0..7): ring of 4 stages x 16KB; re-arms a
//    stage the moment its empty barrier (count=8) fires. NEVER block-syncs
//    inside the loop.
//  - pack warps (wp<8): per stage, read own 256B sub-span of each of 8
//    slices, ballot-pack into own 2 packed words, arrive empty[s].
//  - ONE pack-warps-only named barrier per chunk (before phase B);
//    packed[] ping-pong removes the trailing barrier.
//  - phase B: 240 uniform off-diag tile units; scores folded into pack.
// Last block: reduce + exact-integer NMS + state reset.
// ---------------------------------------------------------------------------
__global__ __launch_bounds__(NTHR, 3) void fused_nms_kernel(
    const float* __restrict__ mask, float* __restrict__ out)
{
    const unsigned sbase = su32(smem);
    unsigned (*packed)[CHUNK_WORDS][NINST] =
        (unsigned (*)[CHUNK_WORDS][NINST])(smem + SM_PACKED);
    volatile int* s_done = (volatile int*)(smem + SM_DONE);
    auto full_mb  = [&](int s) { return sbase + SM_MBAR + 8 * s; };
    auto empty_mb = [&](int s) { return sbase + SM_MBAR + 32 + 8 * s; };

    const int tid  = threadIdx.x;
    const int lane = tid & 31;
    const int wp   = tid >> 5;               // 0..8

    if (tid == 0) {
        for (int s = 0; s < DEPTH; s++) {
            mbar_init(full_mb(s), 1);
            mbar_init(empty_mb(s), 8);       // one arrive per pack warp
        }
        fence_async();
    }
    __syncthreads();   // all 9 warps: mbarriers visible

    // Static chunk range.
    const int c0 = (int)(((long long)blockIdx.x * NCHUNK) / NBLK);
    const int c1 = (int)(((long long)(blockIdx.x + 1) * NCHUNK) / NBLK);
    const int nstage = (c1 - c0) * 8;

    if (wp == 8) {
        // =================== producer warp (lanes 0..7) ===================
        if (lane < 8) {
            for (int n = 0; n < nstage; n++) {
                const int s = n & 3;
                if (n >= DEPTH) mbar_wait(empty_mb(s), ((n >> 2) - 1) & 1);
                if (lane == 0) mbar_expect_tx(full_mb(s), STAGE_BYTES);
                __syncwarp(0x000000ffu);
                const int c = c0 + (n >> 3), g = n & 7;
                const float* src =
                    mask + (size_t)c * CHUNK_VOX + (size_t)(g * 8 + lane) * V;
                tma_bulk(sbase + SM_RAW + s * STAGE_BYTES + lane * CHUNK_BYTES,
                         src, CHUNK_BYTES, full_mb(s));
            }
        }
    } else {
        // =================== pack warps + phase B ===================
        // triangle decode (tid<240): tile k=tid>>1 (a<b), words [8h,8h+8)
        int i0 = 0, j0 = 4, w0 = 0;
        if (tid < 240) {
            int k = tid >> 1, a = 0, rem = k;
            while (rem >= 15 - a) { rem -= 15 - a; a++; }
            i0 = a * 4; j0 = (a + 1 + rem) * 4;
            w0 = (tid & 1) * 8;
        }
        unsigned acc[4][4];
#pragma unroll
        for (int r = 0; r < 4; r++)
#pragma unroll
            for (int c2 = 0; c2 < 4; c2++) acc[r][c2] = 0u;
        unsigned sc0 = 0, sc1 = 0;

        // warp sub-span: bytes [wp*256, wp*256+256) of each instance slice
        const unsigned rd0 = sbase + SM_RAW + (unsigned)(wp * 256 + lane * 8);
        int gl = 0;

        for (int c = c0; c < c1; c++) {
            const int buf = c & 1;
#pragma unroll 1
            for (int g = 0; g < 8; g++, gl++) {
                const int s = gl & 3;
                mbar_wait(full_mb(s), (gl >> 2) & 1);
                const unsigned rb = rd0 + (unsigned)s * STAGE_BYTES;
#pragma unroll
                for (int jj = 0; jj < 8; jj++) {
                    uint2 v;
                    asm volatile("ld.shared.v2.u32 {%0,%1}, [%2];"
                                 : "=r"(v.x), "=r"(v.y)
                                 : "r"(rb + (unsigned)jj * CHUNK_BYTES));
                    // fixed even/odd voxel permutation, identical for all
                    // instances -> pairwise popcounts and scores unaffected
                    unsigned b0 = __ballot_sync(0xffffffffu, v.x != 0u);
                    unsigned b1 = __ballot_sync(0xffffffffu, v.y != 0u);
                    const int j = g * 8 + jj;
                    if (lane == jj) {
                        packed[buf][wp * 2][j]     = b0;
                        packed[buf][wp * 2 + 1][j] = b1;
                    }
                    unsigned p = __popc(b0) + __popc(b1);
                    if (j < 32) { if (lane == j)        sc0 += p; }
                    else        { if (lane == (j - 32)) sc1 += p; }
                }
                __syncwarp();                 // all lanes' reads done
                if (lane == 0) mbar_arrive(empty_mb(s));   // release
            }
            pack_barrier();   // pack warps only: packed[buf] columns visible

            if (tid < 240) {
#pragma unroll
                for (int w = 0; w < 8; w += 2) {
                    uint4 A0 = *(const uint4*)&packed[buf][w0 + w][i0];
                    uint4 B0 = *(const uint4*)&packed[buf][w0 + w][j0];
                    uint4 A1 = *(const uint4*)&packed[buf][w0 + w + 1][i0];
                    uint4 B1 = *(const uint4*)&packed[buf][w0 + w + 1][j0];
                    unsigned a0[4] = {A0.x, A0.y, A0.z, A0.w};
                    unsigned b0[4] = {B0.x, B0.y, B0.z, B0.w};
                    unsigned a1[4] = {A1.x, A1.y, A1.z, A1.w};
                    unsigned b1[4] = {B1.x, B1.y, B1.z, B1.w};
#pragma unroll
                    for (int r = 0; r < 4; r++)
#pragma unroll
                        for (int c2 = 0; c2 < 4; c2++)
                            acc[r][c2] += __popc(a0[r] & b0[c2]) +
                                          __popc(a1[r] & b1[c2]);
                }
            }
            // no trailing barrier: pack(c+1) targets packed[buf^1]; a write
            // to packed[buf] (pack(c+2)) follows pack_barrier(c+1), which
            // every pack warp reaches only after finishing phase B(c).
        }

        // flush per-block totals
        unsigned* gp =
            g_partial + (unsigned)(blockIdx.x & (NSLOT - 1)) * (NINST * NINST);
        if (tid < 240) {
#pragma unroll
            for (int r = 0; r < 4; r++)
#pragma unroll
                for (int c2 = 0; c2 < 4; c2++)
                    atomicAdd(&gp[(i0 + r) * NINST + (j0 + c2)], acc[r][c2]);
        }
        unsigned* gs = g_score + (unsigned)(blockIdx.x & (NSLOT - 1)) * NINST;
        atomicAdd(&gs[lane], sc0);
        atomicAdd(&gs[lane + 32], sc1);
    }

    // ============ completion + fused tail (ALL warps reach) ============
    __threadfence();
    __syncthreads();
    if (tid == 0) *s_done = (int)atomicAdd(&g_done, 1u);
    __syncthreads();
    if (*s_done != NBLK - 1) return;

    unsigned* inter = (unsigned*)smem;            // 16 KB (raw area is dead)
    unsigned* ssc   = (unsigned*)(smem + 16384);

    {   // reduce NSLOT slots (L1-bypassing)
        const uint4* gp4 = (const uint4*)g_partial;
        uint4* in4 = (uint4*)inter;
        for (int e = tid; e < (NINST * NINST) / 4; e += NTHR) {
            uint4 s = make_uint4(0u, 0u, 0u, 0u);
#pragma unroll
            for (int k = 0; k < NSLOT; k++) {
                uint4 w = __ldcg(&gp4[k * (NINST * NINST / 4) + e]);
                s.x += w.x; s.y += w.y; s.z += w.z; s.w += w.w;
            }
            in4[e] = s;
        }
        if (tid < NINST) {
            unsigned s = 0;
#pragma unroll
            for (int k = 0; k < NSLOT; k++)
                s += __ldcg(&g_score[k * NINST + tid]);
            ssc[tid] = s;
        }
    }
    __syncthreads();

    {   // symmetrize (lower-triangle tiles were never written -> max copy)
        for (int e = tid; e < NINST * NINST; e += NTHR) {
            int i = e >> 6, j = e & 63;
            if (i > j) {
                unsigned hi = inter[j * NINST + i];
                unsigned lo = inter[e];
                inter[e] = hi > lo ? hi : lo;
            }
        }
    }

    {   // reset device state for the next graph replay
        uint4 z = make_uint4(0u, 0u, 0u, 0u);
        uint4* gz = (uint4*)g_partial;
        for (int e = tid; e < (NSLOT * NINST * NINST) / 4; e += NTHR) gz[e] = z;
        if (tid < NSLOT * NINST) g_score[tid] = 0u;
        if (tid == 0) g_done = 0u;
    }
    __syncthreads();

    if (tid < 32) {
        const unsigned sj0 = ssc[lane];
        const unsigned sj1 = ssc[lane + 32];
        unsigned long long ind = ~0ULL;

        for (int i = 0; i < NINST; i++) {
            if (!((ind >> i) & 1ULL)) continue;   // warp-uniform
            const unsigned si  = ssc[i];
            const unsigned in0 = inter[i * NINST + lane];
            const unsigned in1 = inter[i * NINST + lane + 32];
            // iou > 0.5 <=> 2*inter > union (exact integers; counts < 2^23)
            const bool h0 = (2u * in0 > si + sj0 - in0);
            const bool h1 = (2u * in1 > si + sj1 - in1);
            unsigned a0 = __ballot_sync(0xffffffffu, h0 && (si > sj0));
            unsigned a1 = __ballot_sync(0xffffffffu, h1 && (si > sj1));
            unsigned c0m = __ballot_sync(0xffffffffu, h0 && (sj0 > si));
            unsigned c1m = __ballot_sync(0xffffffffu, h1 && (sj1 > si));
            unsigned long long A  = ((unsigned long long)a1 << 32) | a0;
            unsigned long long Bm = ((unsigned long long)c1m << 32) | c0m;
            if (A) {
                int jb = __ffsll((long long)A) - 1;    // first break j
                unsigned long long before = (1ULL << jb) - 1ULL;
                if (Bm & before) ind &= ~(1ULL << i);  // earlier j beat i
                ind &= ~(1ULL << jb);
            } else if (Bm) {
                ind &= ~(1ULL << i);
            }
        }
        out[lane]      = (float)((ind >> lane) & 1ULL);
        out[lane + 32] = (float)((ind >> (lane + 32)) & 1ULL);
    }
}

// ---------------------------------------------------------------------------
extern "C" void kernel_launch(void* const* d_in, const int* in_sizes, int n_in,
                              void* d_out, int out_size) {
    const float* mask = (const float*)d_in[0];
    static bool attr_done = false;
    if (!attr_done) {
        cudaFuncSetAttribute(fused_nms_kernel,
                             cudaFuncAttributeMaxDynamicSharedMemorySize,
                             SMEM_REQ);
        cudaFuncSetAttribute(fused_nms_kernel,
                             cudaFuncAttributePreferredSharedMemoryCarveout,
                             cudaSharedmemCarveoutMaxShared);
        attr_done = true;
    }
    fused_nms_kernel<<<NBLK, NTHR, SMEM_REQ>>>(mask, (float*)d_out);
}